// round 14
// baseline (speedup 1.0000x reference)
#include <cuda_runtime.h>
#include <cuda_bf16.h>
#include <math.h>
#include <stdint.h>

// ---------------------------------------------------------------- constants
#define NUM_CODES 4096
#define D 64
#define HW 4096
#define N_VEC 32768

#define OFF_ZQ   0
#define OFF_LOSS 2097152
#define OFF_PERP 2097153
#define OFF_ENC  2097154ULL
#define ENC_ELEMS 134217728ULL
#define OFF_IND  (OFF_ENC + ENC_ELEMS)
#define OUT_FULL (OFF_IND + N_VEC)
#define BETA 0.25f

// 2-term bf16 split: [z_hi|z_lo] . w_hi   (K = 128; score = z . bf16(w))
#define KSTEPS 4             // 4 kt, each kt does k16 of B, A hi+lo halves
#define AROW_BYTES 256       // 128 bf16 per A row
#define BROW_BYTES 128       // 64 bf16 per B row
#define NCH 64               // codes per chunk
#define NCHUNKS 64
#define MROWS 128            // rows per CTA
#define A_TILE_BYTES 32768   // 128 x 256
#define B_TILE_BYTES 8192    // 64 x 128
#define TAU 0.10f            // fixup margin (err sigma ~0.0096 -> ~10 sigma)

// smem layout
#define SM_A 0
#define SM_B0 32768
#define SM_B1 40960
#define SM_WSQ 49152         // full wsq, 16 KB
#define SM_TOTAL 66048

// ---------------------------------------------------------------- scratch
__device__ float g_wsq[NUM_CODES];
__device__ int   g_idx[N_VEC];
__device__ int   g_counts[NUM_CODES];
__device__ float g_loss;
__device__ int   g_nflag;
__device__ int   g_flag[N_VEC];
__device__ unsigned char g_zimg[256u * A_TILE_BYTES];  // 8.4 MB swizzled A tiles
__device__ unsigned char g_wimg[64u * B_TILE_BYTES];   // 512 KB swizzled B chunks

// ---------------------------------------------------------------- helpers
__device__ __forceinline__ uint32_t smem_u32(const void* p) {
    uint32_t a;
    asm("{ .reg .u64 t; cvta.to.shared.u64 t, %1; cvt.u32.u64 %0, t; }" : "=r"(a) : "l"(p));
    return a;
}
__device__ __forceinline__ void cp16(uint32_t dst, const void* src) {
    asm volatile("cp.async.cg.shared.global [%0], [%1], 16;" :: "r"(dst), "l"(src));
}
__device__ __forceinline__ void ldsm4(uint32_t& r0, uint32_t& r1, uint32_t& r2,
                                      uint32_t& r3, uint32_t addr) {
    asm volatile("ldmatrix.sync.aligned.m8n8.x4.shared.b16 {%0,%1,%2,%3}, [%4];"
                 : "=r"(r0), "=r"(r1), "=r"(r2), "=r"(r3) : "r"(addr));
}
__device__ __forceinline__ void mma16816(float* c, const uint32_t* a,
                                         uint32_t b0, uint32_t b1) {
    asm volatile("mma.sync.aligned.m16n8k16.row.col.f32.bf16.bf16.f32 "
                 "{%0,%1,%2,%3}, {%4,%5,%6,%7}, {%8,%9}, {%0,%1,%2,%3};"
                 : "+f"(c[0]), "+f"(c[1]), "+f"(c[2]), "+f"(c[3])
                 : "r"(a[0]), "r"(a[1]), "r"(a[2]), "r"(a[3]), "r"(b0), "r"(b1));
}
__device__ __forceinline__ uint32_t pack_hi(float a, float b) {
    __nv_bfloat162 h = __floats2bfloat162_rn(a, b);
    return *(uint32_t*)&h;
}
__device__ __forceinline__ float bf_res(float v) {   // v - bf16(v)
    __nv_bfloat16 h = __float2bfloat16(v);
    return v - __bfloat162float(h);
}

// ---------------------------------------------------------------- prep (all-in-one)
// blocks 0..255: A image tiles; 256..319: B chunk images; 320..351: wsq + init
__global__ __launch_bounds__(256) void prep_all(const float* __restrict__ z,
                                                const float* __restrict__ w) {
    __shared__ float Zs[128 * 65];
    int tid = threadIdx.x;

    if (blockIdx.x < 256) {
        int nbase = blockIdx.x * 128;
        int b = nbase >> 12, hw0 = nbase & 4095;
        const float* zb = z + (size_t)b * 262144 + hw0;
        for (int e = tid; e < 128 * 64; e += 256) {
            int c = e >> 7, r = e & 127;
            Zs[r * 65 + c] = zb[(size_t)c * HW + r];
        }
        __syncthreads();
        unsigned char* img = g_zimg + (size_t)blockIdx.x * A_TILE_BYTES;
        for (int e = tid; e < 128 * 64; e += 256) {   // 64 pairs per row
            int r = e >> 6, p = e & 63;
            int k = p * 2;                            // 0..126
            int src = (k < 64) ? k : (k - 64);
            int lo = (k >= 64);
            float v0 = Zs[r * 65 + src], v1 = Zs[r * 65 + src + 1];
            if (lo) { v0 = bf_res(v0); v1 = bf_res(v1); }
            uint32_t off = r * AROW_BYTES + (((k >> 3) ^ (r & 7)) << 4) + (k & 7) * 2;
            *(uint32_t*)(img + off) = pack_hi(v0, v1);
        }
    } else if (blockIdx.x < 320) {
        int ch = blockIdx.x - 256;
        unsigned char* img = g_wimg + (size_t)ch * B_TILE_BYTES;
        int cbase = ch * NCH;
        for (int e = tid; e < NCH * 32; e += 256) {   // 32 pairs per row (k 0..63)
            int r = e >> 5, p = e & 31;
            int k = p * 2;
            const float* wr = w + (size_t)(cbase + r) * D;
            float v0 = wr[k], v1 = wr[k + 1];
            uint32_t off = r * BROW_BYTES + (((k >> 3) ^ (r & 7)) << 4) + (k & 7) * 2;
            *(uint32_t*)(img + off) = pack_hi(v0, v1);
        }
    } else {
        int blk = blockIdx.x - 320;
        int lane = tid & 31, wp = tid >> 5;
        #pragma unroll
        for (int rep = 0; rep < 16; rep++) {
            int code = blk * 128 + rep * 8 + wp;
            const float* row = w + (size_t)code * D;
            float s = 0.f;
            #pragma unroll
            for (int j = 0; j < D; j += 32) { float v = row[j + lane]; s += v * v; }
            #pragma unroll
            for (int o = 16; o; o >>= 1) s += __shfl_xor_sync(0xffffffffu, s, o);
            if (lane == 0) g_wsq[code] = 0.5f * s;
        }
        if (tid < 128) g_counts[blk * 128 + tid] = 0;
        if (blk == 0 && tid == 0) { g_loss = 0.f; g_nflag = 0; }
    }
}

// ---------------------------------------------------------------- main argmax (HMMA)
// 256 CTAs x 256 threads; 128 rows x 4096 codes (64 chunks of 64), K=128 2-term.
// A hi/lo halves share B fragments. Software-pipelined; fused enc zeroing.
__global__ __launch_bounds__(256, 2) void argmax_mma(float* __restrict__ out,
                                                     int full) {
    extern __shared__ char smem[];
    uint32_t sb = smem_u32(smem);
    int tid = threadIdx.x;
    int warp = tid >> 5, lane = tid & 31;
    int nbase = blockIdx.x * MROWS;
    float* wsq_s = (float*)(smem + SM_WSQ);

    // per-CTA encodings slice
    float* encs = out + OFF_ENC + (size_t)nbase * NUM_CODES;
    float4* enc4 = (float4*)(encs + 2);      // 16B-aligned body
    const float4 zero4 = make_float4(0.f, 0.f, 0.f, 0.f);

    // async-load A tile + B chunk 0 + full wsq
    const char* gA = (const char*)g_zimg + (size_t)blockIdx.x * A_TILE_BYTES;
    #pragma unroll
    for (int i = 0; i < 8; i++)
        cp16(sb + SM_A + (tid + 256 * i) * 16, gA + (size_t)(tid + 256 * i) * 16);
    #pragma unroll
    for (int i = 0; i < 2; i++)
        cp16(sb + SM_B0 + (tid + 256 * i) * 16, (const char*)g_wimg + (size_t)(tid + 256 * i) * 16);
    #pragma unroll
    for (int i = 0; i < 4; i++)
        cp16(sb + SM_WSQ + (tid + 256 * i) * 16, (const float4*)g_wsq + tid + 256 * i);
    asm volatile("cp.async.commit_group;" ::: "memory");

    if (full && tid < 2) {                   // enc head/tail floats
        encs[tid] = 0.f;
        encs[(size_t)MROWS * NUM_CODES - 2 + tid] = 0.f;
    }
    asm volatile("cp.async.wait_group 0;" ::: "memory");
    __syncthreads();

    // ldmatrix lane geometry
    int grp = lane >> 3, l7 = lane & 7;
    int mw = warp * 16;
    int arow = mw + ((grp & 1) << 3) + l7;
    int acgrp = grp >> 1;
    uint32_t aRowAddr = sb + SM_A + arow * AROW_BYTES;
    int armask = arow & 7;
    int brow_off = ((grp >> 1) << 3) + l7;
    int bcgrp = grp & 1;
    int qcol = (lane & 3) * 2;

    float best0 = -3.0e38f, sec0 = -3.0e38f, best1 = -3.0e38f, sec1 = -3.0e38f;
    int idx0 = 0, idx1 = 0;

    for (int c = 0; c < NCHUNKS; c++) {
        uint32_t Bb = sb + ((c & 1) ? SM_B1 : SM_B0);
        if (c + 1 < NCHUNKS) {   // prefetch next chunk into other buffer
            uint32_t Bn = sb + (((c + 1) & 1) ? SM_B1 : SM_B0);
            const char* gBn = (const char*)g_wimg + (size_t)(c + 1) * B_TILE_BYTES;
            #pragma unroll
            for (int i = 0; i < 2; i++)
                cp16(Bn + (tid + 256 * i) * 16, gBn + (size_t)(tid + 256 * i) * 16);
            asm volatile("cp.async.commit_group;" ::: "memory");
        }

        // fire-and-forget zeroing of own encodings slice (8 STG.128/thread)
        if (full) {
            #pragma unroll
            for (int s = 0; s < 8; s++) {
                size_t idx = (size_t)(c * 8 + s) * 256 + tid;
                if (idx < ((size_t)MROWS * NUM_CODES - 4) / 4) enc4[idx] = zero4;
            }
        }

        float acc[8][4];
        #pragma unroll
        for (int j = 0; j < 8; j++) {
            acc[j][0] = 0.f; acc[j][1] = 0.f; acc[j][2] = 0.f; acc[j][3] = 0.f;
        }

        // software-pipelined over kt (A hi+lo share B frags)
        uint32_t ah[4], al[4], bq[4][4];
        {
            ldsm4(ah[0], ah[1], ah[2], ah[3], aRowAddr + ((acgrp ^ armask) << 4));
            ldsm4(al[0], al[1], al[2], al[3], aRowAddr + (((8 + acgrp) ^ armask) << 4));
            #pragma unroll
            for (int nb = 0; nb < 4; nb++) {
                int br = nb * 16 + brow_off;
                ldsm4(bq[nb][0], bq[nb][1], bq[nb][2], bq[nb][3],
                      Bb + br * BROW_BYTES + ((bcgrp ^ l7) << 4));
            }
        }
        #pragma unroll
        for (int kt = 0; kt < KSTEPS; kt++) {
            uint32_t ahn[4], aln[4], bn[4][4];
            if (kt + 1 < KSTEPS) {
                int ck = 2 * (kt + 1) + acgrp;
                ldsm4(ahn[0], ahn[1], ahn[2], ahn[3], aRowAddr + ((ck ^ armask) << 4));
                ldsm4(aln[0], aln[1], aln[2], aln[3], aRowAddr + (((8 + ck) ^ armask) << 4));
                int ckb = 2 * (kt + 1) + bcgrp;
                #pragma unroll
                for (int nb = 0; nb < 4; nb++) {
                    int br = nb * 16 + brow_off;
                    ldsm4(bn[nb][0], bn[nb][1], bn[nb][2], bn[nb][3],
                          Bb + br * BROW_BYTES + ((ckb ^ l7) << 4));
                }
            }
            #pragma unroll
            for (int nb = 0; nb < 4; nb++) {
                mma16816(acc[2 * nb],     ah, bq[nb][0], bq[nb][1]);
                mma16816(acc[2 * nb + 1], ah, bq[nb][2], bq[nb][3]);
                mma16816(acc[2 * nb],     al, bq[nb][0], bq[nb][1]);
                mma16816(acc[2 * nb + 1], al, bq[nb][2], bq[nb][3]);
            }
            if (kt + 1 < KSTEPS) {
                #pragma unroll
                for (int q = 0; q < 4; q++) { ah[q] = ahn[q]; al[q] = aln[q]; }
                #pragma unroll
                for (int nb = 0; nb < 4; nb++)
                    #pragma unroll
                    for (int q = 0; q < 4; q++) bq[nb][q] = bn[nb][q];
            }
        }

        // fused argmax epilogue
        int codebase = c * NCH;
        #pragma unroll
        for (int j = 0; j < 8; j++) {
            int n = codebase + 8 * j + qcol;
            float q0 = wsq_s[n], q1 = wsq_s[n + 1];
            float s;
            s = acc[j][0] - q0;
            if (s > best0) { sec0 = best0; best0 = s; idx0 = n; } else sec0 = fmaxf(sec0, s);
            s = acc[j][1] - q1;
            if (s > best0) { sec0 = best0; best0 = s; idx0 = n + 1; } else sec0 = fmaxf(sec0, s);
            s = acc[j][2] - q0;
            if (s > best1) { sec1 = best1; best1 = s; idx1 = n; } else sec1 = fmaxf(sec1, s);
            s = acc[j][3] - q1;
            if (s > best1) { sec1 = best1; best1 = s; idx1 = n + 1; } else sec1 = fmaxf(sec1, s);
        }

        if (c + 1 < NCHUNKS) asm volatile("cp.async.wait_group 0;" ::: "memory");
        __syncthreads();
    }

    // quad reduce (lanes of a quad cover different cols, same rows)
    #pragma unroll
    for (int o = 1; o <= 2; o <<= 1) {
        float ob = __shfl_xor_sync(0xffffffffu, best0, o);
        int   oi = __shfl_xor_sync(0xffffffffu, idx0, o);
        float os = __shfl_xor_sync(0xffffffffu, sec0, o);
        if (ob > best0 || (ob == best0 && oi < idx0)) {
            sec0 = fmaxf(best0, os); best0 = ob; idx0 = oi;
        } else sec0 = fmaxf(sec0, ob);
        ob = __shfl_xor_sync(0xffffffffu, best1, o);
        oi = __shfl_xor_sync(0xffffffffu, idx1, o);
        os = __shfl_xor_sync(0xffffffffu, sec1, o);
        if (ob > best1 || (ob == best1 && oi < idx1)) {
            sec1 = fmaxf(best1, os); best1 = ob; idx1 = oi;
        } else sec1 = fmaxf(sec1, ob);
    }
    if ((lane & 3) == 0) {
        int r0 = nbase + mw + (lane >> 2);
        g_idx[r0] = idx0;
        if (best0 - sec0 < TAU) { int p = atomicAdd(&g_nflag, 1); g_flag[p] = r0; }
        int r1 = r0 + 8;
        g_idx[r1] = idx1;
        if (best1 - sec1 < TAU) { int p = atomicAdd(&g_nflag, 1); g_flag[p] = r1; }
    }
}

// ---------------------------------------------------------------- fp32 fixup
__global__ __launch_bounds__(256) void fixup_kernel(const float* __restrict__ z,
                                                    const float* __restrict__ w) {
    __shared__ float zl[64];
    __shared__ float sv[256];
    __shared__ int   si[256];
    int nf = g_nflag;
    for (int f = blockIdx.x; f < nf; f += gridDim.x) {
        int n = g_flag[f];
        int b = n >> 12, hw = n & 4095;
        if (threadIdx.x < 64)
            zl[threadIdx.x] = z[(size_t)b * 262144 + (size_t)threadIdx.x * HW + hw];
        __syncthreads();
        float best = -3.0e38f; int bidx = 0;
        for (int k = threadIdx.x; k < NUM_CODES; k += 256) {
            const float* wr = w + (size_t)k * D;
            float s = 0.f;
            #pragma unroll 8
            for (int d = 0; d < D; d++) s += zl[d] * wr[d];
            s -= g_wsq[k];
            if (s > best) { best = s; bidx = k; }
        }
        sv[threadIdx.x] = best; si[threadIdx.x] = bidx;
        __syncthreads();
        for (int st = 128; st; st >>= 1) {
            if (threadIdx.x < st) {
                float ov = sv[threadIdx.x + st]; int oi = si[threadIdx.x + st];
                if (ov > sv[threadIdx.x] ||
                    (ov == sv[threadIdx.x] && oi < si[threadIdx.x])) {
                    sv[threadIdx.x] = ov; si[threadIdx.x] = oi;
                }
            }
            __syncthreads();
        }
        if (threadIdx.x == 0) g_idx[n] = si[0];
        __syncthreads();
    }
}

// ---------------------------------------------------------------- pass2 + finalize
__global__ __launch_bounds__(256) void pass2_kernel(const float* __restrict__ z,
                                                    const float* __restrict__ w,
                                                    float* __restrict__ out) {
    int n = blockIdx.x * 256 + threadIdx.x;
    int idx = g_idx[n];
    int b = n >> 12, hw = n & 4095;
    const float* zb = z + (size_t)b * 262144 + hw;
    float* zq = out + OFF_ZQ + (size_t)b * 262144 + hw;
    const float* wr = w + (size_t)idx * D;
    float ls = 0.f;
    #pragma unroll 8
    for (int c = 0; c < D; c++) {
        float wv = wr[c];
        float zv = zb[(size_t)c * HW];
        float d = wv - zv;
        ls += d * d;
        zq[(size_t)c * HW] = wv;
    }
    out[OFF_ENC + (size_t)n * NUM_CODES + (size_t)idx] = 1.0f;
    out[OFF_IND + (size_t)n] = (float)idx;
    atomicAdd(&g_counts[idx], 1);
    __shared__ float red[256];
    red[threadIdx.x] = ls;
    __syncthreads();
    for (int s = 128; s; s >>= 1) {
        if (threadIdx.x < s) red[threadIdx.x] += red[threadIdx.x + s];
        __syncthreads();
    }
    if (threadIdx.x == 0) atomicAdd(&g_loss, red[0]);
}

__global__ __launch_bounds__(256) void pass2_zq_only(const float* __restrict__ w,
                                                     float* __restrict__ out) {
    int n = blockIdx.x * 256 + threadIdx.x;
    int idx = g_idx[n];
    int b = n >> 12, hw = n & 4095;
    float* zq = out + (size_t)b * 262144 + hw;
    const float* wr = w + (size_t)idx * D;
    #pragma unroll 8
    for (int c = 0; c < D; c++) zq[(size_t)c * HW] = wr[c];
}

__global__ void finalize_kernel(float* __restrict__ out) {
    __shared__ float red[256];
    float s = 0.f;
    for (int k = threadIdx.x; k < NUM_CODES; k += 256) {
        float p = (float)g_counts[k] * (1.0f / 32768.0f);
        s += p * logf(p + 1e-10f);
    }
    red[threadIdx.x] = s;
    __syncthreads();
    for (int st = 128; st; st >>= 1) {
        if (threadIdx.x < st) red[threadIdx.x] += red[threadIdx.x + st];
        __syncthreads();
    }
    if (threadIdx.x == 0) {
        out[OFF_PERP] = expf(-red[0]);
        out[OFF_LOSS] = BETA * g_loss * (1.0f / 2097152.0f);
    }
}

// ---------------------------------------------------------------- launch
extern "C" void kernel_launch(void* const* d_in, const int* in_sizes, int n_in,
                              void* d_out, int out_size) {
    const float* z = (const float*)d_in[0];
    const float* w = (const float*)d_in[1];
    float* out = (float*)d_out;

    cudaFuncSetAttribute(argmax_mma, cudaFuncAttributeMaxDynamicSharedMemorySize,
                         SM_TOTAL);

    int full = ((unsigned long long)out_size >= OUT_FULL);

    prep_all<<<352, 256>>>(z, w);
    argmax_mma<<<N_VEC / MROWS, 256, SM_TOTAL>>>(out, full);
    fixup_kernel<<<128, 256>>>(z, w);

    if (full) {
        pass2_kernel<<<N_VEC / 256, 256>>>(z, w, out);
        finalize_kernel<<<1, 256>>>(out);
    } else {
        pass2_zq_only<<<N_VEC / 256, 256>>>(w, out);
    }
}

// round 17
// speedup vs baseline: 6.8894x; 6.8894x over previous
#include <cuda_runtime.h>
#include <cuda_bf16.h>
#include <math.h>
#include <stdint.h>

// ---------------------------------------------------------------- constants
#define NUM_CODES 4096
#define D 64
#define HW 4096
#define N_VEC 32768

#define OFF_ZQ   0
#define OFF_LOSS 2097152
#define OFF_PERP 2097153
#define OFF_ENC  2097154ULL
#define ENC_ELEMS 134217728ULL
#define OFF_IND  (OFF_ENC + ENC_ELEMS)
#define OUT_FULL (OFF_IND + N_VEC)
#define BETA 0.25f

// 2-term bf16 split: [z_hi|z_lo] . w_hi   (K = 128; score = z . bf16(w))
#define KSTEPS 4             // 4 kt; each kt: B k16 frags shared by A hi+lo
#define AROW_BYTES 256       // 128 bf16 per A row
#define BROW_BYTES 128       // 64 bf16 per B row
#define NCH 64               // codes per chunk
#define NCHUNKS 64
#define MROWS 128            // rows per CTA
#define A_TILE_BYTES 32768   // 128 x 256
#define B_TILE_BYTES 8192    // 64 x 128
#define TAU 0.10f            // fixup margin (passed in R14 with exact indices)

// smem layout
#define SM_A 0
#define SM_B0 32768
#define SM_B1 40960
#define SM_WSQ 49152         // full wsq, 16 KB
#define SM_TOTAL 66048

// ---------------------------------------------------------------- scratch
__device__ float g_wsq[NUM_CODES];
__device__ int   g_idx[N_VEC];
__device__ int   g_counts[NUM_CODES];
__device__ float g_loss;
__device__ int   g_nflag;
__device__ int   g_flag[N_VEC];
__device__ unsigned char g_zimg[256u * A_TILE_BYTES];  // 8.4 MB swizzled A tiles
__device__ unsigned char g_wimg[64u * B_TILE_BYTES];   // 512 KB swizzled B chunks

// ---------------------------------------------------------------- helpers
__device__ __forceinline__ uint32_t smem_u32(const void* p) {
    uint32_t a;
    asm("{ .reg .u64 t; cvta.to.shared.u64 t, %1; cvt.u32.u64 %0, t; }" : "=r"(a) : "l"(p));
    return a;
}
__device__ __forceinline__ void cp16(uint32_t dst, const void* src) {
    asm volatile("cp.async.cg.shared.global [%0], [%1], 16;" :: "r"(dst), "l"(src));
}
__device__ __forceinline__ void ldsm4(uint32_t& r0, uint32_t& r1, uint32_t& r2,
                                      uint32_t& r3, uint32_t addr) {
    asm volatile("ldmatrix.sync.aligned.m8n8.x4.shared.b16 {%0,%1,%2,%3}, [%4];"
                 : "=r"(r0), "=r"(r1), "=r"(r2), "=r"(r3) : "r"(addr));
}
__device__ __forceinline__ void mma16816(float* c, const uint32_t* a,
                                         uint32_t b0, uint32_t b1) {
    asm volatile("mma.sync.aligned.m16n8k16.row.col.f32.bf16.bf16.f32 "
                 "{%0,%1,%2,%3}, {%4,%5,%6,%7}, {%8,%9}, {%0,%1,%2,%3};"
                 : "+f"(c[0]), "+f"(c[1]), "+f"(c[2]), "+f"(c[3])
                 : "r"(a[0]), "r"(a[1]), "r"(a[2]), "r"(a[3]), "r"(b0), "r"(b1));
}
__device__ __forceinline__ uint32_t pack_hi(float a, float b) {
    __nv_bfloat162 h = __floats2bfloat162_rn(a, b);
    return *(uint32_t*)&h;
}
__device__ __forceinline__ float bf_res(float v) {   // v - bf16(v)
    __nv_bfloat16 h = __float2bfloat16(v);
    return v - __bfloat162float(h);
}

// ---------------------------------------------------------------- prep (all-in-one)
// blocks 0..255: A image tiles; 256..319: B chunk images; 320..351: wsq + init
__global__ __launch_bounds__(256) void prep_all(const float* __restrict__ z,
                                                const float* __restrict__ w) {
    __shared__ float Zs[128 * 65];
    int tid = threadIdx.x;

    if (blockIdx.x < 256) {
        int nbase = blockIdx.x * 128;
        int b = nbase >> 12, hw0 = nbase & 4095;
        const float* zb = z + (size_t)b * 262144 + hw0;
        for (int e = tid; e < 128 * 64; e += 256) {
            int c = e >> 7, r = e & 127;
            Zs[r * 65 + c] = zb[(size_t)c * HW + r];
        }
        __syncthreads();
        unsigned char* img = g_zimg + (size_t)blockIdx.x * A_TILE_BYTES;
        for (int e = tid; e < 128 * 64; e += 256) {   // 64 pairs per row
            int r = e >> 6, p = e & 63;
            int k = p * 2;                            // 0..126
            int src = (k < 64) ? k : (k - 64);
            int lo = (k >= 64);
            float v0 = Zs[r * 65 + src], v1 = Zs[r * 65 + src + 1];
            if (lo) { v0 = bf_res(v0); v1 = bf_res(v1); }
            uint32_t off = r * AROW_BYTES + (((k >> 3) ^ (r & 7)) << 4) + (k & 7) * 2;
            *(uint32_t*)(img + off) = pack_hi(v0, v1);
        }
    } else if (blockIdx.x < 320) {
        int ch = blockIdx.x - 256;
        unsigned char* img = g_wimg + (size_t)ch * B_TILE_BYTES;
        int cbase = ch * NCH;
        for (int e = tid; e < NCH * 32; e += 256) {   // 32 pairs per row (k 0..63)
            int r = e >> 5, p = e & 31;
            int k = p * 2;
            const float* wr = w + (size_t)(cbase + r) * D;
            float v0 = wr[k], v1 = wr[k + 1];
            uint32_t off = r * BROW_BYTES + (((k >> 3) ^ (r & 7)) << 4) + (k & 7) * 2;
            *(uint32_t*)(img + off) = pack_hi(v0, v1);
        }
    } else {
        int blk = blockIdx.x - 320;
        int lane = tid & 31, wp = tid >> 5;
        #pragma unroll
        for (int rep = 0; rep < 16; rep++) {
            int code = blk * 128 + rep * 8 + wp;
            const float* row = w + (size_t)code * D;
            float s = 0.f;
            #pragma unroll
            for (int j = 0; j < D; j += 32) { float v = row[j + lane]; s += v * v; }
            #pragma unroll
            for (int o = 16; o; o >>= 1) s += __shfl_xor_sync(0xffffffffu, s, o);
            if (lane == 0) g_wsq[code] = 0.5f * s;
        }
        if (tid < 128) g_counts[blk * 128 + tid] = 0;
        if (blk == 0 && tid == 0) { g_loss = 0.f; g_nflag = 0; }
    }
}

// ---------------------------------------------------------------- main argmax (HMMA)
// 256 CTAs x 256 threads; 128 rows x 4096 codes (64 chunks of 64), K=128 2-term.
// A hi/lo halves share B frags; MMA order keeps dependency distance 8.
__global__ __launch_bounds__(256, 2) void argmax_mma(float* __restrict__ out,
                                                     int full) {
    extern __shared__ char smem[];
    uint32_t sb = smem_u32(smem);
    int tid = threadIdx.x;
    int warp = tid >> 5, lane = tid & 31;
    int nbase = blockIdx.x * MROWS;
    float* wsq_s = (float*)(smem + SM_WSQ);

    // per-CTA encodings slice
    float* encs = out + OFF_ENC + (size_t)nbase * NUM_CODES;
    float4* enc4 = (float4*)(encs + 2);      // 16B-aligned body
    const float4 zero4 = make_float4(0.f, 0.f, 0.f, 0.f);

    // async-load A tile + B chunk 0 + full wsq
    const char* gA = (const char*)g_zimg + (size_t)blockIdx.x * A_TILE_BYTES;
    #pragma unroll
    for (int i = 0; i < 8; i++)
        cp16(sb + SM_A + (tid + 256 * i) * 16, gA + (size_t)(tid + 256 * i) * 16);
    #pragma unroll
    for (int i = 0; i < 2; i++)
        cp16(sb + SM_B0 + (tid + 256 * i) * 16, (const char*)g_wimg + (size_t)(tid + 256 * i) * 16);
    #pragma unroll
    for (int i = 0; i < 4; i++)
        cp16(sb + SM_WSQ + (tid + 256 * i) * 16, (const float4*)g_wsq + tid + 256 * i);
    asm volatile("cp.async.commit_group;" ::: "memory");

    if (full && tid < 2) {                   // enc head/tail floats
        encs[tid] = 0.f;
        encs[(size_t)MROWS * NUM_CODES - 2 + tid] = 0.f;
    }
    asm volatile("cp.async.wait_group 0;" ::: "memory");
    __syncthreads();

    // ldmatrix lane geometry
    int grp = lane >> 3, l7 = lane & 7;
    int mw = warp * 16;
    int arow = mw + ((grp & 1) << 3) + l7;
    int acgrp = grp >> 1;
    uint32_t aRowAddr = sb + SM_A + arow * AROW_BYTES;
    int armask = arow & 7;
    int brow_off = ((grp >> 1) << 3) + l7;
    int bcgrp = grp & 1;
    int qcol = (lane & 3) * 2;

    float best0 = -3.0e38f, sec0 = -3.0e38f, best1 = -3.0e38f, sec1 = -3.0e38f;
    int idx0 = 0, idx1 = 0;

    for (int c = 0; c < NCHUNKS; c++) {
        uint32_t Bb = sb + ((c & 1) ? SM_B1 : SM_B0);
        if (c + 1 < NCHUNKS) {   // prefetch next chunk into other buffer
            uint32_t Bn = sb + (((c + 1) & 1) ? SM_B1 : SM_B0);
            const char* gBn = (const char*)g_wimg + (size_t)(c + 1) * B_TILE_BYTES;
            #pragma unroll
            for (int i = 0; i < 2; i++)
                cp16(Bn + (tid + 256 * i) * 16, gBn + (size_t)(tid + 256 * i) * 16);
            asm volatile("cp.async.commit_group;" ::: "memory");
        }

        // fire-and-forget zeroing of own encodings slice (8 STG.128/thread)
        if (full) {
            #pragma unroll
            for (int s = 0; s < 8; s++) {
                size_t idx = (size_t)(c * 8 + s) * 256 + tid;
                if (idx < ((size_t)MROWS * NUM_CODES - 4) / 4) enc4[idx] = zero4;
            }
        }

        float acc[8][4];
        #pragma unroll
        for (int j = 0; j < 8; j++) {
            acc[j][0] = 0.f; acc[j][1] = 0.f; acc[j][2] = 0.f; acc[j][3] = 0.f;
        }

        // software-pipelined over kt (A hi+lo share B frags)
        uint32_t ah[4], al[4], bq[4][4];
        {
            ldsm4(ah[0], ah[1], ah[2], ah[3], aRowAddr + ((acgrp ^ armask) << 4));
            ldsm4(al[0], al[1], al[2], al[3], aRowAddr + (((8 + acgrp) ^ armask) << 4));
            #pragma unroll
            for (int nb = 0; nb < 4; nb++) {
                int br = nb * 16 + brow_off;
                ldsm4(bq[nb][0], bq[nb][1], bq[nb][2], bq[nb][3],
                      Bb + br * BROW_BYTES + ((bcgrp ^ l7) << 4));
            }
        }
        #pragma unroll
        for (int kt = 0; kt < KSTEPS; kt++) {
            uint32_t ahn[4], aln[4], bn[4][4];
            if (kt + 1 < KSTEPS) {
                int ck = 2 * (kt + 1) + acgrp;
                ldsm4(ahn[0], ahn[1], ahn[2], ahn[3], aRowAddr + ((ck ^ armask) << 4));
                ldsm4(aln[0], aln[1], aln[2], aln[3], aRowAddr + (((8 + ck) ^ armask) << 4));
                int ckb = 2 * (kt + 1) + bcgrp;
                #pragma unroll
                for (int nb = 0; nb < 4; nb++) {
                    int br = nb * 16 + brow_off;
                    ldsm4(bn[nb][0], bn[nb][1], bn[nb][2], bn[nb][3],
                          Bb + br * BROW_BYTES + ((ckb ^ l7) << 4));
                }
            }
            // dependency distance 8: all hi MMAs, then all lo MMAs
            #pragma unroll
            for (int nb = 0; nb < 4; nb++) {
                mma16816(acc[2 * nb],     ah, bq[nb][0], bq[nb][1]);
                mma16816(acc[2 * nb + 1], ah, bq[nb][2], bq[nb][3]);
            }
            #pragma unroll
            for (int nb = 0; nb < 4; nb++) {
                mma16816(acc[2 * nb],     al, bq[nb][0], bq[nb][1]);
                mma16816(acc[2 * nb + 1], al, bq[nb][2], bq[nb][3]);
            }
            if (kt + 1 < KSTEPS) {
                #pragma unroll
                for (int q = 0; q < 4; q++) { ah[q] = ahn[q]; al[q] = aln[q]; }
                #pragma unroll
                for (int nb = 0; nb < 4; nb++)
                    #pragma unroll
                    for (int q = 0; q < 4; q++) bq[nb][q] = bn[nb][q];
            }
        }

        // fused argmax epilogue
        int codebase = c * NCH;
        #pragma unroll
        for (int j = 0; j < 8; j++) {
            int n = codebase + 8 * j + qcol;
            float q0 = wsq_s[n], q1 = wsq_s[n + 1];
            float s;
            s = acc[j][0] - q0;
            if (s > best0) { sec0 = best0; best0 = s; idx0 = n; } else sec0 = fmaxf(sec0, s);
            s = acc[j][1] - q1;
            if (s > best0) { sec0 = best0; best0 = s; idx0 = n + 1; } else sec0 = fmaxf(sec0, s);
            s = acc[j][2] - q0;
            if (s > best1) { sec1 = best1; best1 = s; idx1 = n; } else sec1 = fmaxf(sec1, s);
            s = acc[j][3] - q1;
            if (s > best1) { sec1 = best1; best1 = s; idx1 = n + 1; } else sec1 = fmaxf(sec1, s);
        }

        if (c + 1 < NCHUNKS) asm volatile("cp.async.wait_group 0;" ::: "memory");
        __syncthreads();
    }

    // quad reduce (lanes of a quad cover different cols, same rows)
    #pragma unroll
    for (int o = 1; o <= 2; o <<= 1) {
        float ob = __shfl_xor_sync(0xffffffffu, best0, o);
        int   oi = __shfl_xor_sync(0xffffffffu, idx0, o);
        float os = __shfl_xor_sync(0xffffffffu, sec0, o);
        if (ob > best0 || (ob == best0 && oi < idx0)) {
            sec0 = fmaxf(best0, os); best0 = ob; idx0 = oi;
        } else sec0 = fmaxf(sec0, ob);
        ob = __shfl_xor_sync(0xffffffffu, best1, o);
        oi = __shfl_xor_sync(0xffffffffu, idx1, o);
        os = __shfl_xor_sync(0xffffffffu, sec1, o);
        if (ob > best1 || (ob == best1 && oi < idx1)) {
            sec1 = fmaxf(best1, os); best1 = ob; idx1 = oi;
        } else sec1 = fmaxf(sec1, ob);
    }
    if ((lane & 3) == 0) {
        int r0 = nbase + mw + (lane >> 2);
        g_idx[r0] = idx0;
        if (best0 - sec0 < TAU) { int p = atomicAdd(&g_nflag, 1); g_flag[p] = r0; }
        int r1 = r0 + 8;
        g_idx[r1] = idx1;
        if (best1 - sec1 < TAU) { int p = atomicAdd(&g_nflag, 1); g_flag[p] = r1; }
    }
}

// ---------------------------------------------------------------- batched fp32 fixup
// 16 flagged rows per block; codebook streamed ONCE per block via smem tiles.
// zs rows padded to 68 floats (272 B = 17x16) so float4 loads stay 16B-aligned.
#define FIXROWS 16
__global__ __launch_bounds__(256) void fixup_kernel(const float* __restrict__ z,
                                                    const float* __restrict__ w) {
    __shared__ float zs[FIXROWS][68];
    __shared__ float ws[128 * 17 * 4];   // [code][17 float4] = 34 KB
    __shared__ float wq[128];
    int nf = g_nflag;
    int tid = threadIdx.x;
    int row = tid >> 4, part = tid & 15;

    for (int bt = blockIdx.x; bt * FIXROWS < nf; bt += gridDim.x) {
        int rows = nf - bt * FIXROWS;
        if (rows > FIXROWS) rows = FIXROWS;
        for (int e = tid; e < rows * 64; e += 256) {
            int r = e >> 6, d = e & 63;
            int n = g_flag[bt * FIXROWS + r];
            int b = n >> 12, hw = n & 4095;
            zs[r][d] = z[(size_t)b * 262144 + (size_t)d * HW + hw];
        }
        __syncthreads();

        float4 zr[16];
        if (row < rows) {
            #pragma unroll
            for (int i = 0; i < 16; i++) zr[i] = *(float4*)&zs[row][i * 4];
        }

        float best = -3.0e38f; int bidx = 0;
        for (int ch = 0; ch < 32; ch++) {
            {
                const float4* src = (const float4*)(w + (size_t)ch * 128 * 64);
                float4* dst = (float4*)ws;
                for (int e = tid; e < 128 * 16; e += 256) {
                    int cc = e >> 4, d4 = e & 15;
                    dst[cc * 17 + d4] = src[e];
                }
                if (tid < 128) wq[tid] = g_wsq[ch * 128 + tid];
            }
            __syncthreads();
            if (row < rows) {
                #pragma unroll 2
                for (int cc = 0; cc < 8; cc++) {
                    int c = cc * 16 + part;              // lane-interleaved codes
                    const float4* wr = (const float4*)ws + c * 17;
                    float s = 0.f;
                    #pragma unroll
                    for (int i = 0; i < 16; i++) {
                        float4 wv = wr[i];
                        s += zr[i].x * wv.x + zr[i].y * wv.y +
                             zr[i].z * wv.z + zr[i].w * wv.w;
                    }
                    s -= wq[c];
                    int code = ch * 128 + c;
                    if (s > best || (s == best && code < bidx)) { best = s; bidx = code; }
                }
            }
            __syncthreads();
        }

        // reduce over the 16 parts of each row (width-16 segments)
        #pragma unroll
        for (int o = 8; o; o >>= 1) {
            float ov = __shfl_down_sync(0xffffffffu, best, o, 16);
            int   oi = __shfl_down_sync(0xffffffffu, bidx, o, 16);
            if (ov > best || (ov == best && oi < bidx)) { best = ov; bidx = oi; }
        }
        if (part == 0 && row < rows) g_idx[g_flag[bt * FIXROWS + row]] = bidx;
        __syncthreads();
    }
}

// ---------------------------------------------------------------- pass2 + finalize
__global__ __launch_bounds__(256) void pass2_kernel(const float* __restrict__ z,
                                                    const float* __restrict__ w,
                                                    float* __restrict__ out) {
    int n = blockIdx.x * 256 + threadIdx.x;
    int idx = g_idx[n];
    int b = n >> 12, hw = n & 4095;
    const float* zb = z + (size_t)b * 262144 + hw;
    float* zq = out + OFF_ZQ + (size_t)b * 262144 + hw;
    const float* wr = w + (size_t)idx * D;
    float ls = 0.f;
    #pragma unroll 8
    for (int c = 0; c < D; c++) {
        float wv = wr[c];
        float zv = zb[(size_t)c * HW];
        float d = wv - zv;
        ls += d * d;
        zq[(size_t)c * HW] = wv;
    }
    out[OFF_ENC + (size_t)n * NUM_CODES + (size_t)idx] = 1.0f;
    out[OFF_IND + (size_t)n] = (float)idx;
    atomicAdd(&g_counts[idx], 1);
    __shared__ float red[256];
    red[threadIdx.x] = ls;
    __syncthreads();
    for (int s = 128; s; s >>= 1) {
        if (threadIdx.x < s) red[threadIdx.x] += red[threadIdx.x + s];
        __syncthreads();
    }
    if (threadIdx.x == 0) atomicAdd(&g_loss, red[0]);
}

__global__ __launch_bounds__(256) void pass2_zq_only(const float* __restrict__ w,
                                                     float* __restrict__ out) {
    int n = blockIdx.x * 256 + threadIdx.x;
    int idx = g_idx[n];
    int b = n >> 12, hw = n & 4095;
    float* zq = out + (size_t)b * 262144 + hw;
    const float* wr = w + (size_t)idx * D;
    #pragma unroll 8
    for (int c = 0; c < D; c++) zq[(size_t)c * HW] = wr[c];
}

__global__ void finalize_kernel(float* __restrict__ out) {
    __shared__ float red[256];
    float s = 0.f;
    for (int k = threadIdx.x; k < NUM_CODES; k += 256) {
        float p = (float)g_counts[k] * (1.0f / 32768.0f);
        s += p * logf(p + 1e-10f);
    }
    red[threadIdx.x] = s;
    __syncthreads();
    for (int st = 128; st; st >>= 1) {
        if (threadIdx.x < st) red[threadIdx.x] += red[threadIdx.x + st];
        __syncthreads();
    }
    if (threadIdx.x == 0) {
        out[OFF_PERP] = expf(-red[0]);
        out[OFF_LOSS] = BETA * g_loss * (1.0f / 2097152.0f);
    }
}

// ---------------------------------------------------------------- launch
extern "C" void kernel_launch(void* const* d_in, const int* in_sizes, int n_in,
                              void* d_out, int out_size) {
    const float* z = (const float*)d_in[0];
    const float* w = (const float*)d_in[1];
    float* out = (float*)d_out;

    cudaFuncSetAttribute(argmax_mma, cudaFuncAttributeMaxDynamicSharedMemorySize,
                         SM_TOTAL);

    int full = ((unsigned long long)out_size >= OUT_FULL);

    prep_all<<<352, 256>>>(z, w);
    argmax_mma<<<N_VEC / MROWS, 256, SM_TOTAL>>>(out, full);
    fixup_kernel<<<148, 256>>>(z, w);

    if (full) {
        pass2_kernel<<<N_VEC / 256, 256>>>(z, w, out);
        finalize_kernel<<<1, 256>>>(out);
    } else {
        pass2_zq_only<<<N_VEC / 256, 256>>>(w, out);
    }
}